// round 1
// baseline (speedup 1.0000x reference)
#include <cuda_runtime.h>

#define NB 32
#define NPTS 512
#define NC 64
#define PIX (NC * NC)          // 4096
#define ROWS (NPTS + 1)        // 513
#define INV2S2 0.0078125f      // 1/(2*8^2)
#define BG_RATIO 0.15f

// Scratch: factorized exp tables. 2 * 32 * 512 * 64 * 4B = 8 MB.
__device__ float g_Ex[NB][NPTS][NC];
__device__ float g_Ey[NB][NPTS][NC];

// ---------------------------------------------------------------------------
// Kernel 1: Ex[b][n][j] = exp(-(x^2 - 2xc + c^2)/(2 sigma^2)), same for Ey.
// Matches the reference's expansion (not (x-c)^2) for numerics parity.
// ---------------------------------------------------------------------------
__global__ void precompute_kernel(const float* __restrict__ points,
                                  const float* __restrict__ cood) {
    int idx = blockIdx.x * blockDim.x + threadIdx.x;   // over NB*NPTS*NC = 1M
    int j = idx & (NC - 1);
    int n = (idx >> 6) & (NPTS - 1);
    int b = idx >> 15;

    float c = cood[j];
    float x = points[((b * NPTS + n) << 1) + 0];
    float y = points[((b * NPTS + n) << 1) + 1];

    float xd = x * x - 2.0f * x * c + c * c;
    float yd = y * y - 2.0f * y * c + c * c;

    g_Ex[b][n][j] = __expf(-xd * INV2S2);
    g_Ey[b][n][j] = __expf(-yd * INV2S2);
}

// ---------------------------------------------------------------------------
// Kernel 2: one CTA per (batch, 16-row i-tile). 256 threads, each owns
// 4 contiguous j-pixels of one i row. Smem: full Ex (128KB) + Ey tile (32KB).
//
// Pass 1: S_k = sum_n Ey[n,i]*Ex[n,j_k], M_k = max_n (product)
// Finalize: min_dis = max(0, -2s^2 * ln M); bg = (d - sqrt(min_dis))^2
//           denom = S + exp(-bg/2s^2); inv = 1/denom
// Pass 2: out[n, pixel] = Ey*Ex*inv   (softmax without explicit max-shift:
//          identical quotient; underflowed terms are true ~e^-70 zeros)
// ---------------------------------------------------------------------------
#define SMEM_BYTES ((NPTS * NC + NPTS * 16) * 4)   // 163840

__global__ __launch_bounds__(256, 1)
void post_prob_kernel(const float* __restrict__ st_sizes,
                      float* __restrict__ out) {
    extern __shared__ float smem[];
    float* sEx = smem;                 // [NPTS][NC]
    float* sEy = smem + NPTS * NC;     // [NPTS][16]

    int b  = blockIdx.x >> 2;
    int i0 = (blockIdx.x & 3) * 16;
    int t  = threadIdx.x;

    // Cooperative smem fill (float4). Ex: 8192 float4, 32 per thread.
    {
        const float4* src = (const float4*)&g_Ex[b][0][0];
        float4*       dst = (float4*)sEx;
#pragma unroll
        for (int k = 0; k < 32; k++)
            dst[t + 256 * k] = src[t + 256 * k];
        // Ey tile: 512 rows x 16 floats (4 float4 each)
        for (int n = t; n < NPTS; n += 256) {
            const float4* s = (const float4*)&g_Ey[b][n][i0];
            float4*       d = (float4*)&sEy[n * 16];
            d[0] = s[0]; d[1] = s[1]; d[2] = s[2]; d[3] = s[3];
        }
    }
    __syncthreads();

    int iloc = t >> 4;        // 0..15
    int jg   = t & 15;        // 0..15 -> j = 4*jg..4*jg+3

    const float4* exv = (const float4*)sEx + jg;   // row stride 16 float4

    float S0 = 0.f, S1 = 0.f, S2 = 0.f, S3 = 0.f;
    float M0 = 0.f, M1 = 0.f, M2 = 0.f, M3 = 0.f;

#pragma unroll 8
    for (int n = 0; n < NPTS; n++) {
        float  ey = sEy[n * 16 + iloc];
        float4 ex = exv[n * 16];
        float p0 = ey * ex.x, p1 = ey * ex.y, p2 = ey * ex.z, p3 = ey * ex.w;
        S0 += p0; S1 += p1; S2 += p2; S3 += p3;
        M0 = fmaxf(M0, p0); M1 = fmaxf(M1, p1);
        M2 = fmaxf(M2, p2); M3 = fmaxf(M3, p3);
    }

    float d = st_sizes[b] * BG_RATIO;

    float inv0, inv1, inv2, inv3, pb0, pb1, pb2, pb3;
    {
        float M[4] = {M0, M1, M2, M3};
        float S[4] = {S0, S1, S2, S3};
        float iv[4], pb[4];
#pragma unroll
        for (int k = 0; k < 4; k++) {
            float m    = fmaxf(M[k], 1e-35f);
            float mind = fmaxf(-128.0f * __logf(m), 0.0f);  // 2*sigma^2 = 128
            float bd   = d - sqrtf(mind);
            float ebg  = __expf(-(bd * bd) * INV2S2);
            iv[k] = 1.0f / (S[k] + ebg);
            pb[k] = ebg * iv[k];
        }
        inv0 = iv[0]; inv1 = iv[1]; inv2 = iv[2]; inv3 = iv[3];
        pb0 = pb[0]; pb1 = pb[1]; pb2 = pb[2]; pb3 = pb[3];
    }

    float* obase = out + (size_t)b * ROWS * PIX + (i0 + iloc) * NC + jg * 4;

    // Background row (row index 512)
    *(float4*)(obase + (size_t)NPTS * PIX) = make_float4(pb0, pb1, pb2, pb3);

    // Pass 2: stream the 512 point rows
#pragma unroll 4
    for (int n = 0; n < NPTS; n++) {
        float  ey = sEy[n * 16 + iloc];
        float4 ex = exv[n * 16];
        float4 o;
        o.x = ey * ex.x * inv0;
        o.y = ey * ex.y * inv1;
        o.z = ey * ex.z * inv2;
        o.w = ey * ex.w * inv3;
        *(float4*)(obase + (size_t)n * PIX) = o;
    }
}

// ---------------------------------------------------------------------------
extern "C" void kernel_launch(void* const* d_in, const int* in_sizes, int n_in,
                              void* d_out, int out_size) {
    const float* points   = (const float*)d_in[0];
    const float* st_sizes = (const float*)d_in[1];
    const float* cood     = (const float*)d_in[2];
    float*       out      = (float*)d_out;

    cudaFuncSetAttribute(post_prob_kernel,
                         cudaFuncAttributeMaxDynamicSharedMemorySize,
                         SMEM_BYTES);

    precompute_kernel<<<(NB * NPTS * NC) / 256, 256>>>(points, cood);
    post_prob_kernel<<<NB * 4, 256, SMEM_BYTES>>>(st_sizes, out);
}